// round 8
// baseline (speedup 1.0000x reference)
#include <cuda_runtime.h>
#include <cuda_bf16.h>
#include <cstdint>

#define BB 4
#define SS 2048
#define DD 2048          // D_IN = D_STATE = D_OUT
#define NH 16
#define HH 128

// ------------------------- global scratch (no allocs) -----------------------
static __device__ float g_xp[(size_t)BB * SS * DD];                  // 64MB
static __device__ __nv_bfloat16 g_xh[(size_t)BB * SS * DD];          // 32MB
static __device__ __nv_bfloat16 g_xl[(size_t)BB * SS * DD];
static __device__ __nv_bfloat16 g_hsh[(size_t)BB * SS * DD];
static __device__ __nv_bfloat16 g_hsl[(size_t)BB * SS * DD];
static __device__ __nv_bfloat16 g_WiTh[(size_t)DD * DD];             // 8MB
static __device__ __nv_bfloat16 g_WiTl[(size_t)DD * DD];
static __device__ __nv_bfloat16 g_WoTh[(size_t)DD * DD];
static __device__ __nv_bfloat16 g_WoTl[(size_t)DD * DD];

typedef unsigned long long ull;

__device__ __forceinline__ ull pack2(float x, float y) {
    ull r; asm("mov.b64 %0, {%1,%2};" : "=l"(r) : "f"(x), "f"(y)); return r;
}
__device__ __forceinline__ float2 unpack2(ull v) {
    float lo, hi; asm("mov.b64 {%0,%1}, %2;" : "=f"(lo), "=f"(hi) : "l"(v));
    return make_float2(lo, hi);
}
__device__ __forceinline__ void fma2(ull& c, ull a, ull b) {
    asm("fma.rn.f32x2 %0, %1, %2, %3;" : "=l"(c) : "l"(a), "l"(b), "l"(c));
}

__device__ __forceinline__ uint32_t smem_u32(const void* p) {
    uint32_t a;
    asm("{ .reg .u64 t; cvta.to.shared.u64 t, %1; cvt.u32.u64 %0, t; }"
        : "=r"(a) : "l"(p));
    return a;
}
__device__ __forceinline__ void cp16(uint32_t s, const void* g) {
    asm volatile("cp.async.cg.shared.global [%0], [%1], 16;"
                 :: "r"(s), "l"(g) : "memory");
}
__device__ __forceinline__ void ldmx4(uint32_t* r, uint32_t addr) {
    asm volatile("ldmatrix.sync.aligned.m8n8.x4.shared.b16 {%0,%1,%2,%3}, [%4];"
                 : "=r"(r[0]), "=r"(r[1]), "=r"(r[2]), "=r"(r[3]) : "r"(addr));
}
__device__ __forceinline__ void mma_bf(float* c, const uint32_t* a,
                                       const uint32_t* b) {
    asm volatile(
        "mma.sync.aligned.m16n8k16.row.col.f32.bf16.bf16.f32 "
        "{%0,%1,%2,%3}, {%4,%5,%6,%7}, {%8,%9}, {%0,%1,%2,%3};"
        : "+f"(c[0]), "+f"(c[1]), "+f"(c[2]), "+f"(c[3])
        : "r"(a[0]), "r"(a[1]), "r"(a[2]), "r"(a[3]), "r"(b[0]), "r"(b[1]));
}

// ---------------------------------------------------------------------------
// elementwise split fp32 -> bf16 (hi, lo)
// ---------------------------------------------------------------------------
__global__ void __launch_bounds__(256)
split_f32(const float4* __restrict__ in, __nv_bfloat162* __restrict__ hi,
          __nv_bfloat162* __restrict__ lo) {
    int i = blockIdx.x * 256 + threadIdx.x;
    float4 v = in[i];
    __nv_bfloat16 h0 = __float2bfloat16(v.x), h1 = __float2bfloat16(v.y);
    __nv_bfloat16 h2 = __float2bfloat16(v.z), h3 = __float2bfloat16(v.w);
    hi[2 * i + 0] = __halves2bfloat162(h0, h1);
    hi[2 * i + 1] = __halves2bfloat162(h2, h3);
    lo[2 * i + 0] = __halves2bfloat162(
        __float2bfloat16(v.x - __bfloat162float(h0)),
        __float2bfloat16(v.y - __bfloat162float(h1)));
    lo[2 * i + 1] = __halves2bfloat162(
        __float2bfloat16(v.z - __bfloat162float(h2)),
        __float2bfloat16(v.w - __bfloat162float(h3)));
}

// ---------------------------------------------------------------------------
// transpose 2048x2048 fp32 + split -> bf16 hi/lo (out[n][k] = in[k][n])
// ---------------------------------------------------------------------------
__global__ void __launch_bounds__(256)
transpose_split(const float* __restrict__ in, __nv_bfloat16* __restrict__ oh,
                __nv_bfloat16* __restrict__ ol) {
    __shared__ float tile[32][33];
    int x = blockIdx.x * 32 + threadIdx.x;
    int y = blockIdx.y * 32 + threadIdx.y;
#pragma unroll
    for (int i = 0; i < 32; i += 8)
        tile[threadIdx.y + i][threadIdx.x] = in[(size_t)(y + i) * DD + x];
    __syncthreads();
    x = blockIdx.y * 32 + threadIdx.x;
    y = blockIdx.x * 32 + threadIdx.y;
#pragma unroll
    for (int i = 0; i < 32; i += 8) {
        float v = tile[threadIdx.x][threadIdx.y + i];
        __nv_bfloat16 h = __float2bfloat16(v);
        oh[(size_t)(y + i) * DD + x] = h;
        ol[(size_t)(y + i) * DD + x] =
            __float2bfloat16(v - __bfloat162float(h));
    }
}

// ---------------------------------------------------------------------------
// 3x bf16-split GEMM: C[M,2048] = A @ BT^T (+bias)
//   CTA tile 256x128, K_tile 32, 8 warps (4m x 2n, warp = 64x64),
//   2-stage cp.async double buffer (known-good control flow).
// ---------------------------------------------------------------------------
#define KT 32
#define PADK 40                         // smem row stride in bf16 (80B)
#define ROWB (PADK * 2)                 // 80
#define OP_AH 0
#define OP_AL 20480                     // 256*80
#define OP_BH 40960
#define OP_BL 51200                     // + 128*80
#define STAGEB 61440
#define NSTAGE 2
#define SMEMB (NSTAGE * STAGEB)         // 122880

template <bool BIAS>
__global__ void __launch_bounds__(256, 1)
gemm_bf3(const __nv_bfloat16* __restrict__ Ah,
         const __nv_bfloat16* __restrict__ Al,
         const __nv_bfloat16* __restrict__ Bh,
         const __nv_bfloat16* __restrict__ Bl,
         const float* __restrict__ bias, float* __restrict__ C) {
    extern __shared__ __align__(128) char smem[];
    const uint32_t sb = smem_u32(smem);
    const int tid = threadIdx.x;
    const int lane = tid & 31;
    const int wid = tid >> 5;
    const int wm = wid & 3;             // 4 m-blocks of 64 rows
    const int wn = wid >> 2;            // 2 n-blocks of 64 cols
    const size_t bm = (size_t)blockIdx.y * 256;
    const size_t bn = (size_t)blockIdx.x * 128;

    // copy mapping: A row = tid (4 chunks), B row = tid>>1 (2 chunks)
    const __nv_bfloat16* gAh = Ah + (bm + tid) * DD;
    const __nv_bfloat16* gAl = Al + (bm + tid) * DD;
    const int brow = tid >> 1;
    const int bc = (tid & 1) * 2;
    const __nv_bfloat16* gBh = Bh + (bn + brow) * DD + bc * 8;
    const __nv_bfloat16* gBl = Bl + (bn + brow) * DD + bc * 8;
    const uint32_t sA = sb + tid * ROWB;
    const uint32_t sB = sb + brow * ROWB + bc * 16;

    // fragment addresses
    const uint32_t aBase = sb + (wm * 64 + (lane & 15)) * ROWB +
                           (lane >> 4) * 16;
    const int n_off = (lane & 7) + ((lane >> 4) & 1) * 8;
    const int k_off = ((lane >> 3) & 1) * 16;
    const uint32_t bBase = sb + OP_BH + (wn * 64 + n_off) * ROWB + k_off;

    float acc[128];
#pragma unroll
    for (int i = 0; i < 128; i++) acc[i] = 0.0f;

    const int ntiles = DD / KT;  // 64

    // stage loader
    auto load_stage = [&](int stage, int t) {
        const uint32_t so = stage * STAGEB;
        const int ko = t * KT;
#pragma unroll
        for (int i = 0; i < 4; i++) {
            cp16(sA + OP_AH + so + i * 16, gAh + ko + i * 8);
            cp16(sA + OP_AL + so + i * 16, gAl + ko + i * 8);
        }
#pragma unroll
        for (int i = 0; i < 2; i++) {
            cp16(sB + OP_BH + so + i * 16, gBh + ko + i * 8);
            cp16(sB + OP_BL + so + i * 16, gBl + ko + i * 8);
        }
        asm volatile("cp.async.commit_group;" ::: "memory");
    };

    load_stage(0, 0);

    for (int t = 0; t < ntiles; t++) {
        asm volatile("cp.async.wait_group 0;" ::: "memory");
        __syncthreads();

        if (t + 1 < ntiles)
            load_stage((t + 1) & 1, t + 1);

        const uint32_t so = (t & 1) * STAGEB;
#pragma unroll
        for (int kk = 0; kk < 2; kk++) {
            uint32_t ah[4][4], al[4][4];
#pragma unroll
            for (int mt = 0; mt < 4; mt++) {
                ldmx4(ah[mt], aBase + so + mt * 16 * ROWB + kk * 32);
                ldmx4(al[mt], aBase + so + OP_AL + mt * 16 * ROWB + kk * 32);
            }
#pragma unroll
            for (int p = 0; p < 4; p++) {
                uint32_t bh[4], bl[4];
                ldmx4(bh, bBase + so + p * 16 * ROWB + kk * 32);
                ldmx4(bl, bBase + so + 10240 + p * 16 * ROWB + kk * 32);
#pragma unroll
                for (int mt = 0; mt < 4; mt++) {
                    float* c0 = &acc[(mt * 8 + 2 * p) * 4];
                    float* c1 = &acc[(mt * 8 + 2 * p + 1) * 4];
                    mma_bf(c0, ah[mt], bh + 0);
                    mma_bf(c1, ah[mt], bh + 2);
                    mma_bf(c0, al[mt], bh + 0);
                    mma_bf(c1, al[mt], bh + 2);
                    mma_bf(c0, ah[mt], bl + 0);
                    mma_bf(c1, ah[mt], bl + 2);
                }
            }
        }
        __syncthreads();
    }

    // epilogue
#pragma unroll
    for (int mt = 0; mt < 4; mt++) {
        const size_t r0 = bm + wm * 64 + mt * 16 + (lane >> 2);
#pragma unroll
        for (int nt = 0; nt < 8; nt++) {
            const size_t col = bn + wn * 64 + nt * 8 + (lane & 3) * 2;
            const float* a = &acc[(mt * 8 + nt) * 4];
            float2 v0 = make_float2(a[0], a[1]);
            float2 v1 = make_float2(a[2], a[3]);
            if (BIAS) {
                float2 bv = *(const float2*)&bias[col];
                v0.x += bv.x; v0.y += bv.y;
                v1.x += bv.x; v1.y += bv.y;
            }
            *(float2*)&C[r0 * DD + col] = v0;
            *(float2*)&C[(r0 + 8) * DD + col] = v1;
        }
    }
}

// ---------------------------------------------------------------------------
// Recurrence: 64 chains, W columns in regs; emits hs as bf16 hi/lo split.
// ---------------------------------------------------------------------------
__global__ void __launch_bounds__(128, 1)
rnn_kernel(const float* __restrict__ xp, const float* __restrict__ init_state,
           const float* __restrict__ state_w,
           __nv_bfloat16* __restrict__ hs_h, __nv_bfloat16* __restrict__ hs_l,
           float* __restrict__ out_state) {
    const int b = blockIdx.x >> 4;
    const int n = blockIdx.x & 15;
    const int j = threadIdx.x;

    __shared__ __align__(16) float h_sh[2][HH];

    ull w2[64];
    const float* W = state_w + (size_t)n * HH * HH + j;
#pragma unroll
    for (int m = 0; m < 64; m++)
        w2[m] = pack2(W[(2 * m) * HH], W[(2 * m + 1) * HH]);

    h_sh[0][j] = init_state[b * DD + n * HH + j];

    const float* xb = xp + ((size_t)b * SS * NH + n) * HH + j;
    __nv_bfloat16* hbh = hs_h + ((size_t)b * SS * NH + n) * HH + j;
    __nv_bfloat16* hbl = hs_l + ((size_t)b * SS * NH + n) * HH + j;

    float xq[8];
#pragma unroll
    for (int p = 0; p < 8; p++) xq[p] = xb[(size_t)p * DD];

    __syncthreads();

    int cur = 0;
    for (int t = 0; t < SS; t++) {
        const ulonglong2* hv = (const ulonglong2*)h_sh[cur];
        ull a0 = 0ull, a1 = 0ull, a2 = 0ull, a3 = 0ull;
#pragma unroll
        for (int m = 0; m < 32; m += 2) {
            ulonglong2 ha = hv[m];
            ulonglong2 hc = hv[m + 1];
            fma2(a0, ha.x, w2[2 * m]);
            fma2(a1, ha.y, w2[2 * m + 1]);
            fma2(a2, hc.x, w2[2 * m + 2]);
            fma2(a3, hc.y, w2[2 * m + 3]);
        }
        float2 f0 = unpack2(a0), f1 = unpack2(a1);
        float2 f2 = unpack2(a2), f3 = unpack2(a3);
        float sum = ((f0.x + f0.y) + (f1.x + f1.y)) +
                    ((f2.x + f2.y) + (f3.x + f3.y));

        float xv = xq[t & 7];
        if (t + 8 < SS) xq[t & 7] = xb[(size_t)(t + 8) * DD];

        float hn = tanhf(sum + xv);
        __nv_bfloat16 hh = __float2bfloat16(hn);
        hbh[(size_t)t * DD] = hh;
        hbl[(size_t)t * DD] = __float2bfloat16(hn - __bfloat162float(hh));

        const int nxt = cur ^ 1;
        h_sh[nxt][j] = hn;
        __syncthreads();
        cur = nxt;
    }

    if (out_state) out_state[b * DD + n * HH + j] = h_sh[cur][j];
}

// ---------------------------------------------------------------------------
extern "C" void kernel_launch(void* const* d_in, const int* in_sizes, int n_in,
                              void* d_out, int out_size) {
    const float* x = (const float*)d_in[0];
    const float* input_state = (const float*)d_in[1];
    const float* Wi = (const float*)d_in[2];
    const float* bias = (const float*)d_in[3];
    const float* state_w = (const float*)d_in[4];
    const float* Wo = (const float*)d_in[5];
    float* out = (float*)d_out;

    float* xp = nullptr;
    __nv_bfloat16 *xh, *xl, *hsh, *hsl, *WiTh, *WiTl, *WoTh, *WoTl;
    cudaGetSymbolAddress((void**)&xp, g_xp);
    cudaGetSymbolAddress((void**)&xh, g_xh);
    cudaGetSymbolAddress((void**)&xl, g_xl);
    cudaGetSymbolAddress((void**)&hsh, g_hsh);
    cudaGetSymbolAddress((void**)&hsl, g_hsl);
    cudaGetSymbolAddress((void**)&WiTh, g_WiTh);
    cudaGetSymbolAddress((void**)&WiTl, g_WiTl);
    cudaGetSymbolAddress((void**)&WoTh, g_WoTh);
    cudaGetSymbolAddress((void**)&WoTl, g_WoTl);

    cudaFuncSetAttribute(gemm_bf3<true>,
                         cudaFuncAttributeMaxDynamicSharedMemorySize, SMEMB);
    cudaFuncSetAttribute(gemm_bf3<false>,
                         cudaFuncAttributeMaxDynamicSharedMemorySize, SMEMB);

    const size_t out_elems = (size_t)BB * SS * DD;
    float* state_out = nullptr;
    if ((size_t)out_size >= out_elems + (size_t)BB * DD)
        state_out = out + out_elems;

    // 0) operand preparation
    split_f32<<<(BB * SS * DD) / 4 / 256, 256>>>(
        (const float4*)x, (__nv_bfloat162*)xh, (__nv_bfloat162*)xl);
    dim3 tgrid(DD / 32, DD / 32), tblk(32, 8);
    transpose_split<<<tgrid, tblk>>>(Wi, WiTh, WiTl);
    transpose_split<<<tgrid, tblk>>>(Wo, WoTh, WoTl);

    dim3 ggrid(DD / 128, (BB * SS) / 256);  // (16, 32) = 512 CTAs
    // 1) xp = x @ Wi + b
    gemm_bf3<true><<<ggrid, 256, SMEMB>>>(xh, xl, WiTh, WiTl, bias, xp);
    // 2) recurrence -> hs (bf16 hi/lo) + final state
    rnn_kernel<<<64, 128>>>(xp, input_state, state_w, hsh, hsl, state_out);
    // 3) out = hs @ Wo
    gemm_bf3<false><<<ggrid, 256, SMEMB>>>(hsh, hsl, WoTh, WoTl, nullptr, out);
}